// round 2
// baseline (speedup 1.0000x reference)
#include <cuda_runtime.h>

#define NN 50000
#define EE 800000
#define INF 128
#define NB 32
#define ADJ_ELEMS 65536   // 256*256
#define H_OFF 65536       // h starts after adj
#define OUT_ELEMS 98304   // 256*256 + 256*128

__device__ __forceinline__ int graph_of(int n) { return (n * NB) / NN; }

// ---- scratch (module globals; no runtime allocation) ----
__device__ float g_neigh[NN * INF];          // 25.6 MB
__device__ float g_Z[(size_t)NN * 384];      // 76.8 MB: [embed(128) | pool logits(256)]
__device__ float g_r[NN * 8];                // block-sparse assignment r
__device__ int   g_counts[NN];
__device__ int   g_off[NN + 1];
__device__ int   g_cursor[NN];
__device__ int2  g_sorted[EE];               // edges sorted by dst: (src, dst)

// ---------------------------------------------------------------- zero
__global__ void k_zero(float* __restrict__ out) {
    int i = blockIdx.x * blockDim.x + threadIdx.x;
    const int total = NN + OUT_ELEMS;
    for (; i < total; i += gridDim.x * blockDim.x) {
        if (i < NN) g_counts[i] = 0;
        else out[i - NN] = 0.0f;
    }
}

// ---------------------------------------------------------------- histogram of dst
__global__ void k_hist(const int* __restrict__ ei) {
    int e = blockIdx.x * 256 + threadIdx.x;
    if (e < EE) atomicAdd(&g_counts[ei[EE + e]], 1);
}

// ---------------------------------------------------------------- exclusive scan (1 block)
__global__ void k_scan() {
    const int CH = 49;  // 1024*49 = 50176 >= NN
    int t = threadIdx.x, lane = t & 31, wid = t >> 5;
    int base = t * CH;
    int s = 0;
    for (int i = 0; i < CH; i++) {
        int idx = base + i;
        if (idx < NN) s += g_counts[idx];
    }
    int orig = s;
    #pragma unroll
    for (int o = 1; o < 32; o <<= 1) {
        int v = __shfl_up_sync(0xFFFFFFFFu, s, o);
        if (lane >= o) s += v;
    }
    __shared__ int ws[32];
    if (lane == 31) ws[wid] = s;
    __syncthreads();
    if (wid == 0) {
        int v = ws[lane];
        #pragma unroll
        for (int o = 1; o < 32; o <<= 1) {
            int u = __shfl_up_sync(0xFFFFFFFFu, v, o);
            if (lane >= o) v += u;
        }
        ws[lane] = v;
    }
    __syncthreads();
    int excl = s - orig + (wid ? ws[wid - 1] : 0);
    int run = excl;
    for (int i = 0; i < CH; i++) {
        int idx = base + i;
        if (idx < NN) {
            g_off[idx] = run;
            g_cursor[idx] = run;
            run += g_counts[idx];
        }
    }
    if (t == 0) g_off[NN] = EE;
}

// ---------------------------------------------------------------- scatter into dst-sorted order
__global__ void k_scatter(const int* __restrict__ ei) {
    int e = blockIdx.x * 256 + threadIdx.x;
    if (e < EE) {
        int s = ei[e], d = ei[EE + e];
        int pos = atomicAdd(&g_cursor[d], 1);
        g_sorted[pos] = make_int2(s, d);
    }
}

// ---------------------------------------------------------------- mean aggregation (warp per dst node)
__global__ void k_neigh(const float* __restrict__ x) {
    int node = blockIdx.x * 8 + (threadIdx.x >> 5);
    if (node >= NN) return;
    int lane = threadIdx.x & 31;
    int b = g_off[node], e = g_off[node + 1];
    float4 acc = make_float4(0.f, 0.f, 0.f, 0.f);
    for (int j = b; j < e; j++) {
        int s = g_sorted[j].x;
        float4 v = *reinterpret_cast<const float4*>(x + (size_t)s * INF + lane * 4);
        acc.x += v.x; acc.y += v.y; acc.z += v.z; acc.w += v.w;
    }
    float inv = 1.0f / (float)max(e - b, 1);
    acc.x *= inv; acc.y *= inv; acc.z *= inv; acc.w *= inv;
    *reinterpret_cast<float4*>(g_neigh + (size_t)node * INF + lane * 4) = acc;
}

// ---------------------------------------------------------------- GEMM: Z = [x|neigh] @ [W_embed|W_pool] + bias
// M=50000 (tiles of 128), K=256, N=384 (3 col-tiles of 128). 256 threads, 8x8 microtile.
__global__ __launch_bounds__(256) void k_gemm(const float* __restrict__ x,
                                              const float* __restrict__ We,
                                              const float* __restrict__ be,
                                              const float* __restrict__ Wp,
                                              const float* __restrict__ bp) {
    __shared__ float As[16][132];
    __shared__ float Bs[16][132];

    int m0 = blockIdx.x * 128;
    int bt = blockIdx.y;
    const float* Wb;
    const float* bias;
    int ldb, col0;
    if (bt == 0) { Wb = We; ldb = 128; col0 = 0;               bias = be; }
    else         { Wb = Wp; ldb = 256; col0 = (bt - 1) * 128;  bias = bp + (bt - 1) * 128; }

    int tid = threadIdx.x;
    int cx = tid & 15, cy = tid >> 4;

    float acc[8][8];
    #pragma unroll
    for (int i = 0; i < 8; i++)
        #pragma unroll
        for (int j = 0; j < 8; j++) acc[i][j] = 0.0f;

    int ra = tid >> 2;          // 0..63
    int ca = (tid & 3) * 4;     // 0,4,8,12
    int rbk = tid >> 5;         // 0..7
    int cb = (tid & 31) * 4;    // 0..124

    for (int kt = 0; kt < 16; kt++) {
        const float* Aarr = (kt < 8) ? x : g_neigh;
        int kbase = (kt & 7) * 16;
        // A tile: 128 rows x 16 k, stored transposed As[k][m]
        #pragma unroll
        for (int h = 0; h < 2; h++) {
            int row = ra + h * 64;
            int n = m0 + row;
            float4 v = make_float4(0.f, 0.f, 0.f, 0.f);
            if (n < NN) v = *reinterpret_cast<const float4*>(Aarr + (size_t)n * 128 + kbase + ca);
            As[ca + 0][row] = v.x;
            As[ca + 1][row] = v.y;
            As[ca + 2][row] = v.z;
            As[ca + 3][row] = v.w;
        }
        // B tile: 16 k x 128 cols
        #pragma unroll
        for (int h = 0; h < 2; h++) {
            int kk = rbk + h * 8;
            float4 v = *reinterpret_cast<const float4*>(Wb + (size_t)(kt * 16 + kk) * ldb + col0 + cb);
            *reinterpret_cast<float4*>(&Bs[kk][cb]) = v;
        }
        __syncthreads();
        #pragma unroll
        for (int kk = 0; kk < 16; kk++) {
            float a[8], bb[8];
            *reinterpret_cast<float4*>(a)      = *reinterpret_cast<const float4*>(&As[kk][cy * 8]);
            *reinterpret_cast<float4*>(a + 4)  = *reinterpret_cast<const float4*>(&As[kk][cy * 8 + 4]);
            *reinterpret_cast<float4*>(bb)     = *reinterpret_cast<const float4*>(&Bs[kk][cx * 8]);
            *reinterpret_cast<float4*>(bb + 4) = *reinterpret_cast<const float4*>(&Bs[kk][cx * 8 + 4]);
            #pragma unroll
            for (int i = 0; i < 8; i++)
                #pragma unroll
                for (int j = 0; j < 8; j++)
                    acc[i][j] += a[i] * bb[j];
        }
        __syncthreads();
    }
    // epilogue: add bias, store
    #pragma unroll
    for (int i = 0; i < 8; i++) {
        int n = m0 + cy * 8 + i;
        if (n >= NN) continue;
        float* zr = g_Z + (size_t)n * 384 + bt * 128 + cx * 8;
        #pragma unroll
        for (int j = 0; j < 8; j += 4) {
            float4 v;
            v.x = acc[i][j + 0] + bias[cx * 8 + j + 0];
            v.y = acc[i][j + 1] + bias[cx * 8 + j + 1];
            v.z = acc[i][j + 2] + bias[cx * 8 + j + 2];
            v.w = acc[i][j + 3] + bias[cx * 8 + j + 3];
            *reinterpret_cast<float4*>(zr + j) = v;
        }
    }
}

// ---------------------------------------------------------------- per-node: softmax -> r, accumulate h
// block = 128 consecutive nodes (spans <= 2 graphs), 4 warps, per-warp SMEM h-accumulator.
__global__ __launch_bounds__(128) void k_node(float* __restrict__ out) {
    __shared__ float acc[4][2048];   // [warp][slot(2) * 8 * 128]
    int tid = threadIdx.x, warp = tid >> 5, lane = tid & 31;
    int n0 = blockIdx.x * 128;
    int g0 = graph_of(n0);
    for (int i = tid; i < 4 * 2048; i += 128) (&acc[0][0])[i] = 0.0f;
    __syncthreads();
    float* ac = acc[warp];

    for (int it = 0; it < 32; it++) {
        int n = n0 + warp * 32 + it;
        if (n >= NN) break;
        const float* zr = g_Z + (size_t)n * 384;
        // lane holds pool-logit columns [lane*8, lane*8+8)
        float l[8];
        float4 q0 = *reinterpret_cast<const float4*>(zr + 128 + lane * 8);
        float4 q1 = *reinterpret_cast<const float4*>(zr + 128 + lane * 8 + 4);
        l[0] = q0.x; l[1] = q0.y; l[2] = q0.z; l[3] = q0.w;
        l[4] = q1.x; l[5] = q1.y; l[6] = q1.z; l[7] = q1.w;
        float mx = l[0];
        #pragma unroll
        for (int j = 1; j < 8; j++) mx = fmaxf(mx, l[j]);
        #pragma unroll
        for (int o = 16; o > 0; o >>= 1) mx = fmaxf(mx, __shfl_xor_sync(0xFFFFFFFFu, mx, o));
        float ex[8], s = 0.0f;
        #pragma unroll
        for (int j = 0; j < 8; j++) { ex[j] = expf(l[j] - mx); s += ex[j]; }
        #pragma unroll
        for (int o = 16; o > 0; o >>= 1) s += __shfl_xor_sync(0xFFFFFFFFu, s, o);
        // pooled p for this lane's 8 columns
        float p[8];
        float inv_s = 1.0f / s;
        float pm = -1e30f;
        #pragma unroll
        for (int j = 0; j < 8; j++) { p[j] = ex[j] * inv_s; pm = fmaxf(pm, p[j]); }
        // second softmax over block (faithful: 248 masked entries contribute exp(0-pm))
        float e2[8], se2 = 0.0f;
        #pragma unroll
        for (int j = 0; j < 8; j++) { e2[j] = expf(p[j] - pm); se2 += e2[j]; }
        float Zf = se2 + 248.0f * expf(-pm);
        float invZ = 1.0f / Zf;
        float ss = se2 * invZ;
        float invd = 1.0f / (ss + 1e-13f);
        float r[8];
        #pragma unroll
        for (int j = 0; j < 8; j++) r[j] = e2[j] * invZ * invd;

        int gn = graph_of(n);
        if (lane == gn) {
            #pragma unroll
            for (int j = 0; j < 8; j++) g_r[n * 8 + j] = r[j];
        }
        float rb[8];
        #pragma unroll
        for (int j = 0; j < 8; j++) rb[j] = __shfl_sync(0xFFFFFFFFu, r[j], gn);

        float4 ev = *reinterpret_cast<const float4*>(zr + lane * 4);
        int slot = gn - g0;
        float* a2 = ac + slot * 1024 + lane * 4;
        #pragma unroll
        for (int a = 0; a < 8; a++) {
            float ra = rb[a];
            float* pp = a2 + a * 128;
            pp[0] += ra * ev.x;
            pp[1] += ra * ev.y;
            pp[2] += ra * ev.z;
            pp[3] += ra * ev.w;
        }
    }
    __syncthreads();
    for (int idx = tid; idx < 2048; idx += 128) {
        float s = acc[0][idx] + acc[1][idx] + acc[2][idx] + acc[3][idx];
        int slot = idx >> 10, rest = idx & 1023, a = rest >> 7, c = rest & 127;
        int gg = g0 + slot;
        if (gg < NB && s != 0.0f)
            atomicAdd(out + H_OFF + ((gg << 3) + a) * 128 + c, s);
    }
}

// ---------------------------------------------------------------- per-edge adj: 8x8 outer products
// block = 2048 dst-sorted edges (dst spans <= 2 graphs), SMEM accumulator keyed by g(dst).
__global__ __launch_bounds__(256) void k_adj(float* __restrict__ out) {
    __shared__ float acc[2 * 2048];  // [slot][row(256) * 8]
    int tid = threadIdx.x;
    for (int i = tid; i < 4096; i += 256) acc[i] = 0.0f;
    __syncthreads();
    int e0 = blockIdx.x * 2048;
    int g0 = graph_of(g_sorted[e0].y);
    int warp = tid >> 5, lane = tid & 31;
    int aL = lane >> 2;          // 0..7
    int b0 = (lane & 3) * 2;     // 0,2,4,6

    for (int i = 0; i < 256; i++) {
        int e = e0 + warp * 256 + i;
        if (e >= EE) break;
        int2 ed = g_sorted[e];
        float v = 0.0f;
        if (lane < 8)       v = g_r[ed.x * 8 + lane];
        else if (lane < 16) v = g_r[ed.y * 8 + (lane - 8)];
        float rs  = __shfl_sync(0xFFFFFFFFu, v, aL);
        float rd0 = __shfl_sync(0xFFFFFFFFu, v, 8 + b0);
        float rd1 = __shfl_sync(0xFFFFFFFFu, v, 8 + b0 + 1);
        int gs = graph_of(ed.x), gd = graph_of(ed.y);
        int slot = gd - g0;
        int row = (gs << 3) + aL;
        float v0 = rs * rd0, v1 = rs * rd1;
        if (slot >= 0 && slot < 2) {
            atomicAdd(&acc[slot * 2048 + row * 8 + b0],     v0);
            atomicAdd(&acc[slot * 2048 + row * 8 + b0 + 1], v1);
        } else {  // pathological span (shouldn't happen with ~25k edges/graph)
            atomicAdd(out + row * 256 + (gd << 3) + b0,     v0);
            atomicAdd(out + row * 256 + (gd << 3) + b0 + 1, v1);
        }
    }
    __syncthreads();
    for (int idx = tid; idx < 4096; idx += 256) {
        float s = acc[idx];
        int slot = idx >> 11, rest = idx & 2047, row = rest >> 3, bc = rest & 7;
        int gg = g0 + slot;
        if (gg < NB && s != 0.0f)
            atomicAdd(out + row * 256 + (gg << 3) + bc, s);
    }
}

// ---------------------------------------------------------------- launch
extern "C" void kernel_launch(void* const* d_in, const int* in_sizes, int n_in,
                              void* d_out, int out_size) {
    const float* x  = (const float*)d_in[0];
    const int*   ei = (const int*)d_in[1];
    // d_in[2] = batch (derived arithmetically, unused)
    const float* We = (const float*)d_in[3];
    const float* be = (const float*)d_in[4];
    const float* Wp = (const float*)d_in[5];
    const float* bp = (const float*)d_in[6];
    float* out = (float*)d_out;

    k_zero<<<290, 512>>>(out);
    k_hist<<<(EE + 255) / 256, 256>>>(ei);
    k_scan<<<1, 1024>>>();
    k_scatter<<<(EE + 255) / 256, 256>>>(ei);
    k_neigh<<<(NN + 7) / 8, 256>>>(x);
    dim3 gemm_grid((NN + 127) / 128, 3);
    k_gemm<<<gemm_grid, 256>>>(x, We, be, Wp, bp);
    k_node<<<(NN + 127) / 128, 128>>>(out);
    k_adj<<<(EE + 2047) / 2048, 256>>>(out);
}

// round 5
// speedup vs baseline: 1.4130x; 1.4130x over previous
#include <cuda_runtime.h>

#define NN 50000
#define NN2 50176          // padded rows for OOB-safe cp.async (zero-init padding)
#define EE 800000
#define INF 128
#define NB 32
#define H_OFF 65536        // h starts after adj (256*256)
#define OUT_ELEMS 98304    // 256*256 + 256*128

__device__ __forceinline__ int graph_of(int n) { return (n * NB) / NN; }

// ---- scratch (module globals; no runtime allocation) ----
__device__ float g_Z[(size_t)NN * 384];        // [embed(128) | pool logits(256)]
__device__ float g_r[NN * 8];                  // block-sparse assignment r
__device__ int   g_counts[NN];
__device__ int   g_off[NN + 1];
__device__ int   g_cursor[NN];
__device__ int2  g_sorted[EE];                 // edges sorted by dst: (src, dst)
__device__ unsigned int g_A32[(size_t)NN2 * 256];  // tf32 image of [x | neigh]
__device__ unsigned int g_BT[384 * 256];           // tf32 W^T: [n][k]

// ================= helpers =================
__device__ __forceinline__ unsigned int smem_u32(const void* p) {
    unsigned int a;
    asm("{ .reg .u64 t; cvta.to.shared.u64 t, %1; cvt.u32.u64 %0, t; }" : "=r"(a) : "l"(p));
    return a;
}
__device__ __forceinline__ unsigned int f2tf32(float v) {
    unsigned int o;
    asm("cvt.rna.tf32.f32 %0, %1;" : "=r"(o) : "f"(v));
    return o;
}
#define CP_ASYNC16(dst, src) \
    asm volatile("cp.async.ca.shared.global [%0], [%1], 16;" :: "r"(dst), "l"(src) : "memory")
#define CP_COMMIT()  asm volatile("cp.async.commit_group;" ::: "memory")
#define CP_WAIT1()   asm volatile("cp.async.wait_group 1;" ::: "memory")
#define CP_WAIT0()   asm volatile("cp.async.wait_group 0;" ::: "memory")

__device__ __forceinline__ void mma16n8k8(float* d, const unsigned* a, const unsigned* b) {
    asm volatile(
        "mma.sync.aligned.m16n8k8.row.col.f32.tf32.tf32.f32 "
        "{%0,%1,%2,%3}, {%4,%5,%6,%7}, {%8,%9}, {%0,%1,%2,%3};"
        : "+f"(d[0]), "+f"(d[1]), "+f"(d[2]), "+f"(d[3])
        : "r"(a[0]), "r"(a[1]), "r"(a[2]), "r"(a[3]), "r"(b[0]), "r"(b[1]));
}

// ---------------------------------------------------------------- zero
__global__ void k_zero(float* __restrict__ out) {
    int i = blockIdx.x * blockDim.x + threadIdx.x;
    const int total = NN + OUT_ELEMS;
    for (; i < total; i += gridDim.x * blockDim.x) {
        if (i < NN) g_counts[i] = 0;
        else out[i - NN] = 0.0f;
    }
}

// ---------------------------------------------------------------- prep X: tf32 image (cols 0..127)
__global__ void k_prepX(const float* __restrict__ x) {
    int i = blockIdx.x * 256 + threadIdx.x;
    if (i < NN * INF) {
        int row = i >> 7, col = i & 127;
        g_A32[(size_t)row * 256 + col] = f2tf32(x[i]);
    }
}

// ---------------------------------------------------------------- prep W: transpose + tf32
__global__ void k_prepW(const float* __restrict__ We, const float* __restrict__ Wp) {
    int idx = blockIdx.x * 256 + threadIdx.x;   // 98304 total
    if (idx >= 384 * 256) return;
    int k = idx & 255, n = idx >> 8;
    float v = (n < 128) ? We[k * 128 + n] : Wp[k * 256 + (n - 128)];
    g_BT[n * 256 + k] = f2tf32(v);
}

// ---------------------------------------------------------------- histogram of dst
__global__ void k_hist(const int* __restrict__ ei) {
    int e = blockIdx.x * 256 + threadIdx.x;
    if (e < EE) atomicAdd(&g_counts[ei[EE + e]], 1);
}

// ---------------------------------------------------------------- exclusive scan (1 block)
__global__ void k_scan() {
    const int CH = 49;
    int t = threadIdx.x, lane = t & 31, wid = t >> 5;
    int base = t * CH;
    int s = 0;
    for (int i = 0; i < CH; i++) {
        int idx = base + i;
        if (idx < NN) s += g_counts[idx];
    }
    int orig = s;
    #pragma unroll
    for (int o = 1; o < 32; o <<= 1) {
        int v = __shfl_up_sync(0xFFFFFFFFu, s, o);
        if (lane >= o) s += v;
    }
    __shared__ int ws[32];
    if (lane == 31) ws[wid] = s;
    __syncthreads();
    if (wid == 0) {
        int v = ws[lane];
        #pragma unroll
        for (int o = 1; o < 32; o <<= 1) {
            int u = __shfl_up_sync(0xFFFFFFFFu, v, o);
            if (lane >= o) v += u;
        }
        ws[lane] = v;
    }
    __syncthreads();
    int excl = s - orig + (wid ? ws[wid - 1] : 0);
    int run = excl;
    for (int i = 0; i < CH; i++) {
        int idx = base + i;
        if (idx < NN) {
            g_off[idx] = run;
            g_cursor[idx] = run;
            run += g_counts[idx];
        }
    }
    if (t == 0) g_off[NN] = EE;
}

// ---------------------------------------------------------------- scatter into dst-sorted order
__global__ void k_scatter(const int* __restrict__ ei) {
    int e = blockIdx.x * 256 + threadIdx.x;
    if (e < EE) {
        int s = ei[e], d = ei[EE + e];
        int pos = atomicAdd(&g_cursor[d], 1);
        g_sorted[pos] = make_int2(s, d);
    }
}

// ---------------------------------------------------------------- mean aggregation -> tf32 cols 128..255
__global__ void k_neigh(const float* __restrict__ x) {
    int node = blockIdx.x * 8 + (threadIdx.x >> 5);
    if (node >= NN) return;
    int lane = threadIdx.x & 31;
    int b = g_off[node], e = g_off[node + 1];
    float4 acc = make_float4(0.f, 0.f, 0.f, 0.f);
    for (int j = b; j < e; j++) {
        int s = g_sorted[j].x;
        float4 v = *reinterpret_cast<const float4*>(x + (size_t)s * INF + lane * 4);
        acc.x += v.x; acc.y += v.y; acc.z += v.z; acc.w += v.w;
    }
    float inv = 1.0f / (float)max(e - b, 1);
    uint4 tv;
    tv.x = f2tf32(acc.x * inv); tv.y = f2tf32(acc.y * inv);
    tv.z = f2tf32(acc.z * inv); tv.w = f2tf32(acc.w * inv);
    *reinterpret_cast<uint4*>(g_A32 + (size_t)node * 256 + 128 + lane * 4) = tv;
}

// ---------------------------------------------------------------- GEMM via mma.sync tf32
// CTA: 128 rows x 128 cols, K=256 in 8 chunks of 32, cp.async double buffer.
// 8 warps in 4(M)x2(N); warp tile 32x64 = 2x8 m16n8k8.
// SMEM (u32 idx): A buf at buf*4608, B buf at 9216 + buf*4608; ld = 36 words.
#define SM_WORDS (2 * 4608 + 2 * 4608)
__global__ __launch_bounds__(256, 2) void k_gemm_mma(const float* __restrict__ be,
                                                     const float* __restrict__ bp) {
    extern __shared__ unsigned int sm[];
    int tid = threadIdx.x, lane = tid & 31, wid = tid >> 5;
    int warp_m = wid >> 1, warp_n = wid & 1;
    int g = lane >> 2, t = lane & 3;
    int m0 = blockIdx.x * 128, bt = blockIdx.y;
    const unsigned int* Bg = g_BT + (size_t)bt * 128 * 256;
    unsigned int sbase = smem_u32(sm);

    float acc[2][8][4];
    #pragma unroll
    for (int mt = 0; mt < 2; mt++)
        #pragma unroll
        for (int nt = 0; nt < 8; nt++)
            #pragma unroll
            for (int j = 0; j < 4; j++) acc[mt][nt][j] = 0.0f;

    // ---- async chunk loader ----
    auto load_chunk = [&](int c, int buf) {
        int k0 = c * 32;
        unsigned int sa = sbase + (buf * 4608) * 4;
        unsigned int sb = sbase + ((9216 + buf * 4608)) * 4;
        #pragma unroll
        for (int i = 0; i < 4; i++) {
            int e = tid + i * 256;             // 0..1023
            int m = e >> 3, kq = e & 7;
            CP_ASYNC16(sa + (m * 36 + kq * 4) * 4,
                       g_A32 + (size_t)(m0 + m) * 256 + k0 + kq * 4);
            CP_ASYNC16(sb + (m * 36 + kq * 4) * 4,
                       Bg + (size_t)m * 256 + k0 + kq * 4);
        }
    };
    auto compute = [&](int buf) {
        const unsigned int* As = sm + buf * 4608;
        const unsigned int* Bs = sm + 9216 + buf * 4608;
        #pragma unroll
        for (int ks = 0; ks < 4; ks++) {
            unsigned int a[2][4], b[8][2];
            #pragma unroll
            for (int mt = 0; mt < 2; mt++) {
                int mb = warp_m * 32 + mt * 16;
                a[mt][0] = As[(mb + g) * 36 + ks * 8 + t];
                a[mt][1] = As[(mb + g + 8) * 36 + ks * 8 + t];
                a[mt][2] = As[(mb + g) * 36 + ks * 8 + t + 4];
                a[mt][3] = As[(mb + g + 8) * 36 + ks * 8 + t + 4];
            }
            #pragma unroll
            for (int nt = 0; nt < 8; nt++) {
                int n = warp_n * 64 + nt * 8 + g;
                b[nt][0] = Bs[n * 36 + ks * 8 + t];
                b[nt][1] = Bs[n * 36 + ks * 8 + t + 4];
            }
            #pragma unroll
            for (int mt = 0; mt < 2; mt++)
                #pragma unroll
                for (int nt = 0; nt < 8; nt++)
                    mma16n8k8(acc[mt][nt], a[mt], b[nt]);
        }
    };

    load_chunk(0, 0); CP_COMMIT();
    load_chunk(1, 1); CP_COMMIT();
    #pragma unroll
    for (int c = 0; c < 8; c++) {
        if (c < 7) { CP_WAIT1(); } else { CP_WAIT0(); }
        __syncthreads();
        compute(c & 1);
        __syncthreads();
        if (c + 2 < 8) { load_chunk(c + 2, c & 1); CP_COMMIT(); }
    }

    // ---- epilogue: bias + store ----
    __syncthreads();
    float* bsh = reinterpret_cast<float*>(sm);
    const float* bias = (bt == 0) ? be : bp + (bt - 1) * 128;
    if (tid < 128) bsh[tid] = bias[tid];
    __syncthreads();
    #pragma unroll
    for (int mt = 0; mt < 2; mt++) {
        int r0 = m0 + warp_m * 32 + mt * 16 + g;
        #pragma unroll
        for (int nt = 0; nt < 8; nt++) {
            int cloc = warp_n * 64 + nt * 8 + 2 * t;
            float bx = bsh[cloc], by = bsh[cloc + 1];
            if (r0 < NN) {
                float2 v = make_float2(acc[mt][nt][0] + bx, acc[mt][nt][1] + by);
                *reinterpret_cast<float2*>(g_Z + (size_t)r0 * 384 + bt * 128 + cloc) = v;
            }
            if (r0 + 8 < NN) {
                float2 v = make_float2(acc[mt][nt][2] + bx, acc[mt][nt][3] + by);
                *reinterpret_cast<float2*>(g_Z + (size_t)(r0 + 8) * 384 + bt * 128 + cloc) = v;
            }
        }
    }
}

// ---------------------------------------------------------------- per-node: softmax -> r, accumulate h
__global__ __launch_bounds__(128) void k_node(float* __restrict__ out) {
    __shared__ float acc[4][2048];   // [warp][slot(2) * 8 * 128]
    int tid = threadIdx.x, warp = tid >> 5, lane = tid & 31;
    int n0 = blockIdx.x * 128;
    int g0 = graph_of(n0);
    for (int i = tid; i < 4 * 2048; i += 128) (&acc[0][0])[i] = 0.0f;
    __syncthreads();
    float* ac = acc[warp];

    for (int it = 0; it < 32; it++) {
        int n = n0 + warp * 32 + it;
        if (n >= NN) break;
        const float* zr = g_Z + (size_t)n * 384;
        float l[8];
        float4 q0 = *reinterpret_cast<const float4*>(zr + 128 + lane * 8);
        float4 q1 = *reinterpret_cast<const float4*>(zr + 128 + lane * 8 + 4);
        l[0] = q0.x; l[1] = q0.y; l[2] = q0.z; l[3] = q0.w;
        l[4] = q1.x; l[5] = q1.y; l[6] = q1.z; l[7] = q1.w;
        float mx = l[0];
        #pragma unroll
        for (int j = 1; j < 8; j++) mx = fmaxf(mx, l[j]);
        #pragma unroll
        for (int o = 16; o > 0; o >>= 1) mx = fmaxf(mx, __shfl_xor_sync(0xFFFFFFFFu, mx, o));
        float ex[8], s = 0.0f;
        #pragma unroll
        for (int j = 0; j < 8; j++) { ex[j] = expf(l[j] - mx); s += ex[j]; }
        #pragma unroll
        for (int o = 16; o > 0; o >>= 1) s += __shfl_xor_sync(0xFFFFFFFFu, s, o);
        float p[8];
        float inv_s = 1.0f / s;
        float pm = -1e30f;
        #pragma unroll
        for (int j = 0; j < 8; j++) { p[j] = ex[j] * inv_s; pm = fmaxf(pm, p[j]); }
        float e2[8], se2 = 0.0f;
        #pragma unroll
        for (int j = 0; j < 8; j++) { e2[j] = expf(p[j] - pm); se2 += e2[j]; }
        float Zf = se2 + 248.0f * expf(-pm);
        float invZ = 1.0f / Zf;
        float ss = se2 * invZ;
        float invd = 1.0f / (ss + 1e-13f);
        float r[8];
        #pragma unroll
        for (int j = 0; j < 8; j++) r[j] = e2[j] * invZ * invd;

        int gn = graph_of(n);
        if (lane == gn) {
            #pragma unroll
            for (int j = 0; j < 8; j++) g_r[n * 8 + j] = r[j];
        }
        float rb[8];
        #pragma unroll
        for (int j = 0; j < 8; j++) rb[j] = __shfl_sync(0xFFFFFFFFu, r[j], gn);

        float4 ev = *reinterpret_cast<const float4*>(zr + lane * 4);
        int slot = gn - g0;
        float4* a4 = reinterpret_cast<float4*>(ac + slot * 1024) + lane;
        #pragma unroll
        for (int a = 0; a < 8; a++) {
            float ra = rb[a];
            float4 t = a4[a * 32];
            t.x = fmaf(ra, ev.x, t.x);
            t.y = fmaf(ra, ev.y, t.y);
            t.z = fmaf(ra, ev.z, t.z);
            t.w = fmaf(ra, ev.w, t.w);
            a4[a * 32] = t;
        }
    }
    __syncthreads();
    for (int idx = tid; idx < 2048; idx += 128) {
        float s = acc[0][idx] + acc[1][idx] + acc[2][idx] + acc[3][idx];
        int slot = idx >> 10, rest = idx & 1023, a = rest >> 7, c = rest & 127;
        int gg = g0 + slot;
        if (gg < NB && s != 0.0f)
            atomicAdd(out + H_OFF + ((gg << 3) + a) * 128 + c, s);
    }
}

// ---------------------------------------------------------------- per-edge adj: 8x8 outer products
__global__ __launch_bounds__(256) void k_adj(float* __restrict__ out) {
    __shared__ float acc[2 * 2048];
    int tid = threadIdx.x;
    for (int i = tid; i < 4096; i += 256) acc[i] = 0.0f;
    __syncthreads();
    int e0 = blockIdx.x * 2048;
    int g0 = graph_of(g_sorted[e0].y);
    int warp = tid >> 5, lane = tid & 31;
    int aL = lane >> 2;
    int b0 = (lane & 3) * 2;

    for (int i = 0; i < 256; i++) {
        int e = e0 + warp * 256 + i;
        if (e >= EE) break;
        int2 ed = g_sorted[e];
        float v = 0.0f;
        if (lane < 8)       v = g_r[ed.x * 8 + lane];
        else if (lane < 16) v = g_r[ed.y * 8 + (lane - 8)];
        float rs  = __shfl_sync(0xFFFFFFFFu, v, aL);
        float rd0 = __shfl_sync(0xFFFFFFFFu, v, 8 + b0);
        float rd1 = __shfl_sync(0xFFFFFFFFu, v, 8 + b0 + 1);
        int gs = graph_of(ed.x), gd = graph_of(ed.y);
        int slot = gd - g0;
        int row = (gs << 3) + aL;
        float v0 = rs * rd0, v1 = rs * rd1;
        if (slot >= 0 && slot < 2) {
            atomicAdd(&acc[slot * 2048 + row * 8 + b0],     v0);
            atomicAdd(&acc[slot * 2048 + row * 8 + b0 + 1], v1);
        } else {
            atomicAdd(out + row * 256 + (gd << 3) + b0,     v0);
            atomicAdd(out + row * 256 + (gd << 3) + b0 + 1, v1);
        }
    }
    __syncthreads();
    for (int idx = tid; idx < 4096; idx += 256) {
        float s = acc[idx];
        int slot = idx >> 11, rest = idx & 2047, row = rest >> 3, bc = rest & 7;
        int gg = g0 + slot;
        if (gg < NB && s != 0.0f)
            atomicAdd(out + row * 256 + (gg << 3) + bc, s);
    }
}

// ---------------------------------------------------------------- launch
extern "C" void kernel_launch(void* const* d_in, const int* in_sizes, int n_in,
                              void* d_out, int out_size) {
    const float* x  = (const float*)d_in[0];
    const int*   ei = (const int*)d_in[1];
    const float* We = (const float*)d_in[3];
    const float* be = (const float*)d_in[4];
    const float* Wp = (const float*)d_in[5];
    const float* bp = (const float*)d_in[6];
    float* out = (float*)d_out;

    static int smem_set = 0;
    if (!smem_set) {
        cudaFuncSetAttribute(k_gemm_mma, cudaFuncAttributeMaxDynamicSharedMemorySize,
                             SM_WORDS * 4);
        smem_set = 1;
    }

    k_zero<<<290, 512>>>(out);
    k_prepX<<<(NN * INF + 255) / 256, 256>>>(x);
    k_prepW<<<384, 256>>>(We, Wp);
    k_hist<<<(EE + 255) / 256, 256>>>(ei);
    k_scan<<<1, 1024>>>();
    k_scatter<<<(EE + 255) / 256, 256>>>(ei);
    k_neigh<<<(NN + 7) / 8, 256>>>(x);
    dim3 gg((NN + 127) / 128, 3);
    k_gemm_mma<<<gg, 256, SM_WORDS * 4>>>(be, bp);
    k_node<<<(NN + 127) / 128, 128>>>(out);
    k_adj<<<(EE + 2047) / 2048, 256>>>(out);
}